// round 5
// baseline (speedup 1.0000x reference)
#include <cuda_runtime.h>
#include <math.h>

#define NGT 32

// Scratch (static device allocations are allowed; no cudaMalloc anywhere).
// Layout: scale-major segments, each segment is B=64 images x N_s keys.
__device__ unsigned int g_negkey[64 * (49152 + 12288 + 3072)];
__device__ int   g_numpos[3 * 64];
__device__ float g_total;

__device__ __forceinline__ float sl1(float x) {
    float ax = fabsf(x);
    return ax < 1.0f ? 0.5f * x * x : ax - 0.5f;
}

__global__ void k_zero() {
    int i = threadIdx.x;
    if (i == 0) g_total = 0.0f;
    if (i < 192) g_numpos[i] = 0;
}

// One thread per anchor. Computes best IoU / argmax over 32 GT boxes
// (division-free inner loop), positive-anchor losses (loc + obj + cls),
// per-(b,scale) positive count, and writes the orderable negative-BCE key.
__global__ __launch_bounds__(256) void k_main(
    const float* __restrict__ pred, const float* __restrict__ anchors,
    const float* __restrict__ gtb, const int* __restrict__ gtl,
    int N, int HW, int sIdx)
{
    __shared__ float sx1[NGT], sy1[NGT], sx2[NGT], sy2[NGT], sar[NGT];
    __shared__ int slab[NGT];

    int b = blockIdx.y;
    int tid = threadIdx.x;
    if (tid < NGT) {
        const float* g = gtb + ((size_t)b * NGT + tid) * 4;
        float x1 = g[0], y1 = g[1], x2 = g[2], y2 = g[3];
        sx1[tid] = x1; sy1[tid] = y1; sx2[tid] = x2; sy2[tid] = y2;
        sar[tid] = (x2 - x1) * (y2 - y1);
        slab[tid] = gtl[b * NGT + tid];
    }
    __syncthreads();

    size_t segoff = (sIdx == 0) ? 0
                  : (sIdx == 1) ? (size_t)64 * 49152
                                : (size_t)64 * (49152 + 12288);

    int n = blockIdx.x * blockDim.x + tid;
    float acc = 0.0f;
    int posc = 0;

    if (n < N) {
        float4 A = __ldg((const float4*)anchors + n);
        float areaA = (A.z - A.x) * (A.w - A.y);

        // g = 0 init (matches argmax first-occurrence semantics)
        float bi, bd;
        int bidx = 0;
        {
            float lx = fmaxf(A.x, sx1[0]);
            float ly = fmaxf(A.y, sy1[0]);
            float rx = fminf(A.z, sx2[0]);
            float ry = fminf(A.w, sy2[0]);
            float w = fmaxf(rx - lx, 0.0f);
            float h = fmaxf(ry - ly, 0.0f);
            bi = w * h;
            bd = areaA + sar[0] - bi + 1e-9f;
        }
        #pragma unroll 8
        for (int g = 1; g < NGT; ++g) {
            float lx = fmaxf(A.x, sx1[g]);
            float ly = fmaxf(A.y, sy1[g]);
            float rx = fminf(A.z, sx2[g]);
            float ry = fminf(A.w, sy2[g]);
            float w = fmaxf(rx - lx, 0.0f);
            float h = fmaxf(ry - ly, 0.0f);
            float inter = w * h;
            float d = areaA + sar[g] - inter + 1e-9f;
            // iou_g > best  <=>  inter*bd > bi*d   (denominators > 0)
            if (inter * bd > bi * d) { bi = inter; bd = d; bidx = g; }
        }
        float best = bi / bd;     // one IEEE division per anchor
        bool pos = best >= 0.5f;
        bool neg = best < 0.4f;

        int hw = n / 3;
        int a  = n - hw * 3;
        const float* pb = pred + ((size_t)(b * 24 + a * 8)) * (size_t)HW + hw;

        float p4 = pb[(size_t)4 * HW];
        float tpos = pos ? 1.0f : 0.0f;
        float obj = fmaxf(p4, 0.0f) - p4 * tpos + log1pf(expf(-fabsf(p4)));

        if (pos) {
            posc = 1;
            float p0 = pb[0];
            float p1 = pb[(size_t)1 * HW];
            float p2 = pb[(size_t)2 * HW];
            float p3 = pb[(size_t)3 * HW];
            float p5 = pb[(size_t)5 * HW];
            float p6 = pb[(size_t)6 * HW];
            float p7 = pb[(size_t)7 * HW];

            float ax = (A.x + A.z) * 0.5f;
            float ay = (A.y + A.w) * 0.5f;
            float aw = fmaxf(A.z - A.x, 1e-6f);
            float ah = fmaxf(A.w - A.y, 1e-6f);
            float m0 = sx1[bidx], m1 = sy1[bidx], m2 = sx2[bidx], m3 = sy2[bidx];
            float gx = (m0 + m2) * 0.5f;
            float gy = (m1 + m3) * 0.5f;
            float gw = fmaxf(m2 - m0, 1e-6f);
            float gh = fmaxf(m3 - m1, 1e-6f);
            float t_tx = (gx - ax) / aw;
            float t_ty = (gy - ay) / ah;
            float t_tw = logf(gw / aw);
            float t_th = logf(gh / ah);
            float loc = sl1(p0 - t_tx) + sl1(p1 - t_ty) + sl1(p2 - t_tw) + sl1(p3 - t_th);

            // cls: cross-entropy via log_softmax over 3 logits
            float m = fmaxf(p5, fmaxf(p6, p7));
            float lse = m + logf(expf(p5 - m) + expf(p6 - m) + expf(p7 - m));
            int tgt = slab[bidx];
            if (tgt < 0) tgt = 0;
            float pt = (tgt == 0) ? p5 : ((tgt == 1) ? p6 : p7);

            acc = loc + obj + (lse - pt);
        }

        // Orderable key: positive floats -> bits | 0x80000000 (monotonic).
        // Non-negative anchors get key 0 (never selected unless k > num_neg,
        // which the select kernel handles).
        unsigned key = 0u;
        if (neg) key = __float_as_uint(obj) | 0x80000000u;
        g_negkey[segoff + (size_t)b * N + n] = key;
    }

    // Block reduction of loss partial + positive count
    float v = acc;
    int pc = posc;
    #pragma unroll
    for (int o = 16; o; o >>= 1) {
        v  += __shfl_down_sync(0xffffffffu, v, o);
        pc += __shfl_down_sync(0xffffffffu, pc, o);
    }
    __shared__ float rs[8];
    __shared__ int   rp[8];
    if ((tid & 31) == 0) { rs[tid >> 5] = v; rp[tid >> 5] = pc; }
    __syncthreads();
    if (tid < 32) {
        v  = (tid < 8) ? rs[tid] : 0.0f;
        pc = (tid < 8) ? rp[tid] : 0;
        #pragma unroll
        for (int o = 4; o; o >>= 1) {
            v  += __shfl_down_sync(0xffffffffu, v, o);
            pc += __shfl_down_sync(0xffffffffu, pc, o);
        }
        if (tid == 0) {
            if (v != 0.0f) atomicAdd(&g_total, v);
            if (pc)        atomicAdd(&g_numpos[sIdx * 64 + b], pc);
        }
    }
}

// One block per (b, scale): 4-pass 8-bit radix select of the k-th largest
// negative key, then sum of all keys strictly above the threshold plus
// (k - count_gt) copies of the threshold value (all ties are equal-valued,
// so tie-breaking order cannot change the sum).
__global__ __launch_bounds__(1024) void k_select()
{
    int b = blockIdx.x;   // 0..63
    int s = blockIdx.y;   // 0..2
    int N = (s == 0) ? 49152 : ((s == 1) ? 12288 : 3072);
    size_t off = (s == 0) ? 0
               : (s == 1) ? (size_t)64 * 49152
                          : (size_t)64 * (49152 + 12288);
    const unsigned* __restrict__ keys = g_negkey + off + (size_t)b * N;

    int np = g_numpos[s * 64 + b];
    int k = 3 * (np > 1 ? np : 1);

    __shared__ unsigned hist[256];
    __shared__ unsigned s_pref;
    __shared__ int s_kr;
    __shared__ float red[32];

    int tid = threadIdx.x;
    unsigned prefix = 0;
    int kr = k;

    for (int pass = 3; pass >= 0; --pass) {
        for (int i = tid; i < 256; i += blockDim.x) hist[i] = 0;
        __syncthreads();
        int shift = pass * 8;
        unsigned himask = (pass == 3) ? 0u : (0xFFFFFFFFu << (shift + 8));
        for (int i = tid; i < N; i += blockDim.x) {
            unsigned key = keys[i];
            if ((key & himask) == prefix) {
                unsigned bkt = (key >> shift) & 255u;
                // warp-aggregate to kill same-bucket shared-atomic contention
                unsigned mm = __match_any_sync(__activemask(), bkt);
                if (((mm >> (tid & 31)) & 1u) && ((tid & 31) == (__ffs(mm) - 1)))
                    atomicAdd(&hist[bkt], (unsigned)__popc(mm));
            }
        }
        __syncthreads();
        if (tid == 0) {
            int cum = 0;
            int v = 255;
            for (; v > 0; --v) {
                int c = (int)hist[v];
                if (cum + c >= kr) break;
                cum += c;
            }
            s_pref = prefix | ((unsigned)v << shift);
            s_kr = kr - cum;
        }
        __syncthreads();
        prefix = s_pref;
        kr = s_kr;
        __syncthreads();
    }

    unsigned T = prefix;   // k-th largest key (or 0 if k > num_neg)
    float sum = 0.0f;
    for (int i = tid; i < N; i += blockDim.x) {
        unsigned key = keys[i];
        if (key > T) sum += __uint_as_float(key & 0x7FFFFFFFu);
    }
    #pragma unroll
    for (int o = 16; o; o >>= 1) sum += __shfl_down_sync(0xffffffffu, sum, o);
    if ((tid & 31) == 0) red[tid >> 5] = sum;
    __syncthreads();
    if (tid < 32) {
        sum = red[tid];
        #pragma unroll
        for (int o = 16; o; o >>= 1) sum += __shfl_down_sync(0xffffffffu, sum, o);
        if (tid == 0) {
            if (T >= 0x80000000u)   // real threshold -> add tie contributions
                sum += (float)kr * __uint_as_float(T & 0x7FFFFFFFu);
            atomicAdd(&g_total, sum);
        }
    }
}

__global__ void k_final(float* out) {
    out[0] = g_total * (1.0f / 64.0f);
}

extern "C" void kernel_launch(void* const* d_in, const int* in_sizes, int n_in,
                              void* d_out, int out_size)
{
    // Identify inputs by element count (all distinct for this problem).
    const float *pred0 = 0, *pred1 = 0, *pred2 = 0;
    const float *anc0 = 0, *anc1 = 0, *anc2 = 0, *gtb = 0;
    const int *gtl = 0;
    for (int i = 0; i < n_in; ++i) {
        switch (in_sizes[i]) {
            case 25165824: pred0 = (const float*)d_in[i]; break; // 64*24*128*128
            case 6291456:  pred1 = (const float*)d_in[i]; break; // 64*24*64*64
            case 1572864:  pred2 = (const float*)d_in[i]; break; // 64*24*32*32
            case 196608:   anc0  = (const float*)d_in[i]; break; // 49152*4
            case 49152:    anc1  = (const float*)d_in[i]; break; // 12288*4
            case 12288:    anc2  = (const float*)d_in[i]; break; // 3072*4
            case 8192:     gtb   = (const float*)d_in[i]; break; // 64*32*4
            case 2048:     gtl   = (const int*)d_in[i];   break; // 64*32
        }
    }

    k_zero<<<1, 256>>>();

    dim3 g0(49152 / 256, 64);
    k_main<<<g0, 256>>>(pred0, anc0, gtb, gtl, 49152, 16384, 0);
    dim3 g1(12288 / 256, 64);
    k_main<<<g1, 256>>>(pred1, anc1, gtb, gtl, 12288, 4096, 1);
    dim3 g2(3072 / 256, 64);
    k_main<<<g2, 256>>>(pred2, anc2, gtb, gtl, 3072, 1024, 2);

    k_select<<<dim3(64, 3), 1024>>>();
    k_final<<<1, 1>>>((float*)d_out);
}

// round 7
// speedup vs baseline: 2.3098x; 2.3098x over previous
#include <cuda_runtime.h>
#include <math.h>

#define NGT 32

// Static scratch (no cudaMalloc anywhere).
// g_negkey layout per (scale,b): [a][HW], monotonic-orderable uint keys.
__device__ unsigned g_negkey[64 * (49152 + 12288 + 3072)];
__device__ unsigned g_hist[3 * 64 * 256];   // fused top-byte histogram
__device__ int   g_numpos[3 * 64];
__device__ float g_total;

__device__ __forceinline__ float sl1(float x) {
    float ax = fabsf(x);
    return ax < 1.0f ? 0.5f * x * x : ax - 0.5f;
}

__global__ void k_zero() {
    int i = blockIdx.x * blockDim.x + threadIdx.x;
    if (i == 0) g_total = 0.0f;
    if (i < 192) g_numpos[i] = 0;
    if (i < 3 * 64 * 256) g_hist[i] = 0;
}

// Tiled matcher: block = 16x16 grid positions of one image/scale; thread = 1
// position x 3 anchor sizes. GTs outside the tile bbox have IoU exactly 0 with
// every anchor in the tile, so they are pruned up front (ballot-compacted,
// index-ascending so argmax-first semantics survive). Anchors are computed in
// registers from the closed form (bit-exact vs the reference _make_anchors:
// every intermediate is exactly representable in fp32).
__global__ __launch_bounds__(256) void k_main(
    const float* __restrict__ pred, const float* __restrict__ gtb,
    const int* __restrict__ gtl, int W, int tilesX, float stride,
    int sIdx, size_t segoff)
{
    __shared__ float sgx1[NGT], sgy1[NGT], sgx2[NGT], sgy2[NGT], sgar[NGT];
    __shared__ int slab[NGT];
    __shared__ int sK;
    __shared__ unsigned hist[256];
    __shared__ float rs[8];
    __shared__ int rp[8];

    int b = blockIdx.y;
    int tile = blockIdx.x;
    int ti = tile / tilesX;
    int tj = tile - ti * tilesX;
    int tid = threadIdx.x;
    int tx = tid & 15, ty = tid >> 4;
    int j = tj * 16 + tx;
    int i = ti * 16 + ty;
    int HW = W * W;

    hist[tid] = 0;

    // GT candidate compaction (warp 0): tile bbox covers the largest anchor
    // extent (half = 2.5*stride). Strict inequalities: touching => IoU 0.
    if (tid < 32) {
        float xlo = (tj * 16 + 0.5f) * stride - 2.5f * stride;
        float xhi = (tj * 16 + 15.5f) * stride + 2.5f * stride;
        float ylo = (ti * 16 + 0.5f) * stride - 2.5f * stride;
        float yhi = (ti * 16 + 15.5f) * stride + 2.5f * stride;
        const float* g = gtb + ((size_t)b * NGT + tid) * 4;
        float gx1 = g[0], gy1 = g[1], gx2 = g[2], gy2 = g[3];
        bool ov = (gx1 < xhi) && (gx2 > xlo) && (gy1 < yhi) && (gy2 > ylo);
        unsigned m = __ballot_sync(0xffffffffu, ov);
        if (ov) {
            int p = __popc(m & ((1u << tid) - 1u));
            sgx1[p] = gx1; sgy1[p] = gy1; sgx2[p] = gx2; sgy2[p] = gy2;
            sgar[p] = (gx2 - gx1) * (gy2 - gy1);
            slab[p] = gtl[b * NGT + tid];
        }
        if (tid == 0) sK = __popc(m);
    }
    __syncthreads();
    int K = sK;

    float cpx = (j + 0.5f) * stride;
    float cpy = (i + 0.5f) * stride;
    float halfv[3] = {1.5f * stride, 2.0f * stride, 2.5f * stride};
    float ax1[3], ay1[3], ax2[3], ay2[3], areaA[3];
    #pragma unroll
    for (int a = 0; a < 3; a++) {
        ax1[a] = cpx - halfv[a]; ax2[a] = cpx + halfv[a];
        ay1[a] = cpy - halfv[a]; ay2[a] = cpy + halfv[a];
        float s2 = 2.0f * halfv[a];
        areaA[a] = s2 * s2;
    }

    // Division-free argmax over candidates; init (0, 1, idx 0) preserves
    // argmax-first semantics when all IoUs are 0.
    float bi[3] = {0.f, 0.f, 0.f}, bd[3] = {1.f, 1.f, 1.f};
    int bx[3] = {0, 0, 0};
    for (int kk = 0; kk < K; kk++) {
        float g1 = sgx1[kk], g2 = sgy1[kk], g3 = sgx2[kk], g4 = sgy2[kk];
        float ga = sgar[kk];
        #pragma unroll
        for (int a = 0; a < 3; a++) {
            float lx = fmaxf(ax1[a], g1);
            float ly = fmaxf(ay1[a], g2);
            float rx = fminf(ax2[a], g3);
            float ry = fminf(ay2[a], g4);
            float w = fmaxf(rx - lx, 0.f);
            float h = fmaxf(ry - ly, 0.f);
            float in = w * h;
            float d = areaA[a] + ga - in + 1e-9f;
            if (in * bd[a] > bi[a] * d) { bi[a] = in; bd[a] = d; bx[a] = kk; }
        }
    }

    float acc = 0.f;
    int posc = 0;
    int hw = i * W + j;
    const float* pbb = pred + (size_t)b * 24 * HW + hw;

    #pragma unroll
    for (int a = 0; a < 3; a++) {
        float best = bi[a] / bd[a];   // one exact IEEE division per anchor
        bool pos = best >= 0.5f;
        bool neg = best < 0.4f;
        const float* pb = pbb + (size_t)(a * 8) * HW;
        float p4 = pb[(size_t)4 * HW];
        float obj = fmaxf(p4, 0.f) - (pos ? p4 : 0.f) + log1pf(expf(-fabsf(p4)));

        if (pos) {
            posc++;
            float p0 = pb[0];
            float p1 = pb[(size_t)HW];
            float p2 = pb[(size_t)2 * HW];
            float p3 = pb[(size_t)3 * HW];
            float p5 = pb[(size_t)5 * HW];
            float p6 = pb[(size_t)6 * HW];
            float p7 = pb[(size_t)7 * HW];
            int m = bx[a];
            float m0 = sgx1[m], m1 = sgy1[m], m2 = sgx2[m], m3 = sgy2[m];
            float ax = (ax1[a] + ax2[a]) * 0.5f;
            float ay = (ay1[a] + ay2[a]) * 0.5f;
            float aw = fmaxf(ax2[a] - ax1[a], 1e-6f);
            float ah = fmaxf(ay2[a] - ay1[a], 1e-6f);
            float gx = (m0 + m2) * 0.5f;
            float gy = (m1 + m3) * 0.5f;
            float gw = fmaxf(m2 - m0, 1e-6f);
            float gh = fmaxf(m3 - m1, 1e-6f);
            float loc = sl1(p0 - (gx - ax) / aw) + sl1(p1 - (gy - ay) / ah)
                      + sl1(p2 - logf(gw / aw)) + sl1(p3 - logf(gh / ah));
            float mx = fmaxf(p5, fmaxf(p6, p7));
            float lse = mx + logf(expf(p5 - mx) + expf(p6 - mx) + expf(p7 - mx));
            int tgt = slab[m]; if (tgt < 0) tgt = 0;
            float pt = (tgt == 0) ? p5 : ((tgt == 1) ? p6 : p7);
            acc += loc + obj + (lse - pt);
        }

        unsigned key = neg ? (__float_as_uint(obj) | 0x80000000u) : 0u;
        g_negkey[segoff + (size_t)b * (3 * HW) + (size_t)a * HW + hw] = key;

        // fused radix pass 3: top-byte histogram (warp-aggregated)
        unsigned bkt = key >> 24;
        unsigned mm = __match_any_sync(0xffffffffu, bkt);
        if ((tid & 31) == __ffs(mm) - 1)
            atomicAdd(&hist[bkt], (unsigned)__popc(mm));
    }

    // Block reduce loss partial + positive count; then flush histogram.
    float v = acc; int pc = posc;
    #pragma unroll
    for (int o = 16; o; o >>= 1) {
        v  += __shfl_down_sync(0xffffffffu, v, o);
        pc += __shfl_down_sync(0xffffffffu, pc, o);
    }
    if ((tid & 31) == 0) { rs[tid >> 5] = v; rp[tid >> 5] = pc; }
    __syncthreads();

    unsigned c = hist[tid];
    if (c) atomicAdd(&g_hist[(sIdx * 64 + b) * 256 + tid], c);

    if (tid < 32) {
        v  = (tid < 8) ? rs[tid] : 0.f;
        pc = (tid < 8) ? rp[tid] : 0;
        #pragma unroll
        for (int o = 4; o; o >>= 1) {
            v  += __shfl_down_sync(0xffffffffu, v, o);
            pc += __shfl_down_sync(0xffffffffu, pc, o);
        }
        if (tid == 0) {
            if (v != 0.f) atomicAdd(&g_total, v);
            if (pc)       atomicAdd(&g_numpos[sIdx * 64 + b], pc);
        }
    }
}

// Parallel byte-select: largest v with suffix-count >= kr (serial-walk
// semantics preserved: falls through to v=0 when the count runs out).
// Executed by warp 0; caller syncs around it.
__device__ __forceinline__ void select256(const unsigned* cnt, int kr,
                                          int* s_v, int* s_kr, int tid)
{
    if (tid < 32) {
        int base = tid * 8;
        int seg = 0;
        #pragma unroll
        for (int t = 0; t < 8; t++) seg += (int)cnt[base + t];
        int incl = seg;
        #pragma unroll
        for (int off = 1; off < 32; off <<= 1) {
            int u = __shfl_down_sync(0xffffffffu, incl, off);
            if (tid + off < 32) incl += u;
        }
        int sufExcl = incl - seg;
        int total = __shfl_sync(0xffffffffu, incl, 0);
        if (sufExcl < kr && incl >= kr) {        // exactly one owner lane
            int cum = sufExcl;
            for (int t = 7; t >= 0; t--) {
                int cc = (int)cnt[base + t];
                if (cum + cc >= kr) { *s_v = base + t; *s_kr = kr - cum; break; }
                cum += cc;
            }
        }
        if (tid == 0 && total < kr) {            // k exceeds total keys
            *s_v = 0; *s_kr = kr - (total - (int)cnt[0]);
        }
    }
}

// One block per (b,scale): radix-select the k-th largest key. Pass 3 is fused
// into k_main; passes 2/1/0 scan the keys once each and simultaneously
// accumulate the sum of keys provably > T (disjoint partition by the level at
// which a key exceeds the running prefix), so no extra sum pass is needed.
__global__ __launch_bounds__(1024) void k_select()
{
    int b = blockIdx.x, s = blockIdx.y;
    int N = (s == 0) ? 49152 : ((s == 1) ? 12288 : 3072);
    size_t off = (s == 0) ? 0
               : (s == 1) ? (size_t)64 * 49152
                          : (size_t)64 * (49152 + 12288);
    const unsigned* __restrict__ keys = g_negkey + off + (size_t)b * N;

    int np = g_numpos[s * 64 + b];
    int k = 3 * (np > 1 ? np : 1);

    __shared__ unsigned cnt[256];
    __shared__ float fsb[256];
    __shared__ int s_v, s_kr;
    __shared__ float red[32];

    int tid = threadIdx.x;
    int lane = tid & 31;
    int n4 = N >> 2;
    const uint4* k4 = (const uint4*)keys;

    // pass 3 from fused histogram
    if (tid < 256) cnt[tid] = g_hist[(s * 64 + b) * 256 + tid];
    __syncthreads();
    select256(cnt, k, &s_v, &s_kr, tid);
    __syncthreads();
    unsigned v3 = (unsigned)s_v;
    int kr = s_kr;
    if (tid < 256) cnt[tid] = 0;
    __syncthreads();

    float lsum = 0.f;

    // pass 2
    for (int idx = tid; idx < n4; idx += 1024) {
        uint4 q = __ldg(k4 + idx);
        unsigned kk[4] = {q.x, q.y, q.z, q.w};
        #pragma unroll
        for (int e = 0; e < 4; e++) {
            unsigned key = kk[e];
            unsigned t = key >> 24;
            if (t > v3) lsum += __uint_as_float(key & 0x7fffffffu);
            else if (t == v3) {
                unsigned bkt = (key >> 16) & 255u;
                unsigned mm = __match_any_sync(__activemask(), bkt);
                if (lane == __ffs(mm) - 1)
                    atomicAdd(&cnt[bkt], (unsigned)__popc(mm));
            }
        }
    }
    __syncthreads();
    select256(cnt, kr, &s_v, &s_kr, tid);
    __syncthreads();
    unsigned p2 = (v3 << 8) | (unsigned)s_v;
    kr = s_kr;
    if (tid < 256) cnt[tid] = 0;
    __syncthreads();

    // pass 1
    for (int idx = tid; idx < n4; idx += 1024) {
        uint4 q = __ldg(k4 + idx);
        unsigned kk[4] = {q.x, q.y, q.z, q.w};
        #pragma unroll
        for (int e = 0; e < 4; e++) {
            unsigned key = kk[e];
            unsigned h = key >> 16;
            if (h == p2) {
                unsigned bkt = (key >> 8) & 255u;
                unsigned mm = __match_any_sync(__activemask(), bkt);
                if (lane == __ffs(mm) - 1)
                    atomicAdd(&cnt[bkt], (unsigned)__popc(mm));
            } else if ((key >> 24) == v3 && h > p2) {
                lsum += __uint_as_float(key & 0x7fffffffu);
            }
        }
    }
    __syncthreads();
    select256(cnt, kr, &s_v, &s_kr, tid);
    __syncthreads();
    unsigned p1 = (p2 << 8) | (unsigned)s_v;
    kr = s_kr;
    if (tid < 256) { cnt[tid] = 0; fsb[tid] = 0.f; }
    __syncthreads();

    // pass 0 (matching keys are few: plain atomics + per-bucket value sums)
    for (int idx = tid; idx < n4; idx += 1024) {
        uint4 q = __ldg(k4 + idx);
        unsigned kk[4] = {q.x, q.y, q.z, q.w};
        #pragma unroll
        for (int e = 0; e < 4; e++) {
            unsigned key = kk[e];
            unsigned q24 = key >> 8;
            if (q24 == p1) {
                unsigned bkt = key & 255u;
                atomicAdd(&cnt[bkt], 1u);
                atomicAdd(&fsb[bkt], __uint_as_float(key & 0x7fffffffu));
            } else if ((key >> 16) == p2 && q24 > p1) {
                lsum += __uint_as_float(key & 0x7fffffffu);
            }
        }
    }
    __syncthreads();
    select256(cnt, kr, &s_v, &s_kr, tid);
    __syncthreads();
    int v0 = s_v;
    int krF = s_kr;
    unsigned T = (p1 << 8) | (unsigned)v0;

    if (tid < 256 && tid > v0) lsum += fsb[tid];

    #pragma unroll
    for (int o = 16; o; o >>= 1) lsum += __shfl_down_sync(0xffffffffu, lsum, o);
    if (lane == 0) red[tid >> 5] = lsum;
    __syncthreads();
    if (tid < 32) {
        float v = red[tid];
        #pragma unroll
        for (int o = 16; o; o >>= 1) v += __shfl_down_sync(0xffffffffu, v, o);
        if (tid == 0) {
            if (T & 0x80000000u)   // real threshold -> ties contribute
                v += (float)krF * __uint_as_float(T & 0x7fffffffu);
            if (v != 0.f) atomicAdd(&g_total, v);
        }
    }
}

__global__ void k_final(float* out) {
    out[0] = g_total * (1.0f / 64.0f);
}

extern "C" void kernel_launch(void* const* d_in, const int* in_sizes, int n_in,
                              void* d_out, int out_size)
{
    const float *pred0 = 0, *pred1 = 0, *pred2 = 0, *gtb = 0;
    const int *gtl = 0;
    for (int i = 0; i < n_in; ++i) {
        switch (in_sizes[i]) {
            case 25165824: pred0 = (const float*)d_in[i]; break; // 64*24*128*128
            case 6291456:  pred1 = (const float*)d_in[i]; break; // 64*24*64*64
            case 1572864:  pred2 = (const float*)d_in[i]; break; // 64*24*32*32
            case 8192:     gtb   = (const float*)d_in[i]; break; // 64*32*4
            case 2048:     gtl   = (const int*)d_in[i];   break; // 64*32
        }
    }

    k_zero<<<48, 1024>>>();

    k_main<<<dim3(64, 64), 256>>>(pred0, gtb, gtl, 128, 8,  8.0f, 0, (size_t)0);
    k_main<<<dim3(16, 64), 256>>>(pred1, gtb, gtl,  64, 4, 16.0f, 1, (size_t)64 * 49152);
    k_main<<<dim3( 4, 64), 256>>>(pred2, gtb, gtl,  32, 2, 32.0f, 2, (size_t)64 * (49152 + 12288));

    k_select<<<dim3(64, 3), 1024>>>();
    k_final<<<1, 1>>>((float*)d_out);
}

// round 10
// speedup vs baseline: 2.5280x; 1.0945x over previous
#include <cuda_runtime.h>
#include <math.h>

#define NGT 32

// Static scratch (no cudaMalloc anywhere). Zero-initialized at load;
// every kernel restores its state to zero each call (graph-replay safe).
__device__ unsigned g_negkey[64 * (49152 + 12288 + 3072)];
__device__ unsigned g_hist[3 * 64 * 256];   // fused top-byte histogram
__device__ int      g_numpos[3 * 64];
__device__ float    g_total;
__device__ unsigned g_done;

__device__ __forceinline__ float sl1(float x) {
    float ax = fabsf(x);
    return ax < 1.0f ? 0.5f * x * x : ax - 0.5f;
}

// Fused matcher: ALL scales in one launch. blockIdx.x in [0,84):
//   [0,64)  scale 0: W=128, stride 8,  tiles 4x16
//   [64,80) scale 1: W=64,  stride 16, tiles 2x8
//   [80,84) scale 2: W=32,  stride 32, tiles 1x4
// Block = 32x8 grid positions of one image; thread = 1 position x 3 sizes.
// GTs outside the tile bbox have IoU exactly 0 with every anchor in the tile,
// so they are pruned up front (ballot-compacted, index-ascending to preserve
// argmax-first semantics). Anchors come from the closed form in registers
// (bit-exact vs the reference _make_anchors).
__global__ __launch_bounds__(256) void k_all(
    const float* __restrict__ p0, const float* __restrict__ p1,
    const float* __restrict__ p2, const float* __restrict__ gtb,
    const int* __restrict__ gtl)
{
    __shared__ float sgx1[NGT], sgy1[NGT], sgx2[NGT], sgy2[NGT], sgar[NGT];
    __shared__ int slab[NGT];
    __shared__ int sK;
    __shared__ unsigned hist[256];
    __shared__ float rs[8];
    __shared__ int rp[8];

    int bs = blockIdx.x;
    int b = blockIdx.y;
    const float* pred;
    int W, tilesX, sIdx, tile;
    float stride;
    size_t segoff;
    if (bs < 64)      { pred = p0; W = 128; tilesX = 4; stride = 8.f;  sIdx = 0; segoff = 0;                            tile = bs; }
    else if (bs < 80) { pred = p1; W = 64;  tilesX = 2; stride = 16.f; sIdx = 1; segoff = (size_t)64 * 49152;           tile = bs - 64; }
    else              { pred = p2; W = 32;  tilesX = 1; stride = 32.f; sIdx = 2; segoff = (size_t)64 * (49152 + 12288); tile = bs - 80; }

    int ti = tile / tilesX;
    int tj = tile - ti * tilesX;
    int tid = threadIdx.x;
    int tx = tid & 31, ty = tid >> 5;
    int j = tj * 32 + tx;
    int i = ti * 8 + ty;
    int HW = W * W;

    hist[tid] = 0;

    // GT candidate compaction (warp 0). Tile bbox covers the largest anchor
    // half-extent (2.5*stride). Strict inequality: touching => IoU 0.
    if (tid < 32) {
        float xlo = (tj * 32 + 0.5f) * stride - 2.5f * stride;
        float xhi = (tj * 32 + 31.5f) * stride + 2.5f * stride;
        float ylo = (ti * 8 + 0.5f) * stride - 2.5f * stride;
        float yhi = (ti * 8 + 7.5f) * stride + 2.5f * stride;
        const float* g = gtb + ((size_t)b * NGT + tid) * 4;
        float gx1 = g[0], gy1 = g[1], gx2 = g[2], gy2 = g[3];
        bool ov = (gx1 < xhi) && (gx2 > xlo) && (gy1 < yhi) && (gy2 > ylo);
        unsigned m = __ballot_sync(0xffffffffu, ov);
        if (ov) {
            int p = __popc(m & ((1u << tid) - 1u));
            sgx1[p] = gx1; sgy1[p] = gy1; sgx2[p] = gx2; sgy2[p] = gy2;
            sgar[p] = (gx2 - gx1) * (gy2 - gy1);
            slab[p] = gtl[b * NGT + tid];
        }
        if (tid == 0) sK = __popc(m);
    }
    __syncthreads();
    int K = sK;

    float cpx = (j + 0.5f) * stride;
    float cpy = (i + 0.5f) * stride;
    float halfv[3] = {1.5f * stride, 2.0f * stride, 2.5f * stride};
    float ax1[3], ay1[3], ax2[3], ay2[3], areaA[3];
    #pragma unroll
    for (int a = 0; a < 3; a++) {
        ax1[a] = cpx - halfv[a]; ax2[a] = cpx + halfv[a];
        ay1[a] = cpy - halfv[a]; ay2[a] = cpy + halfv[a];
        float s2 = 2.0f * halfv[a];
        areaA[a] = s2 * s2;
    }

    // Division-free argmax; init (0, 1, idx 0) preserves argmax-first
    // semantics when all IoUs are 0.
    float bi[3] = {0.f, 0.f, 0.f}, bd[3] = {1.f, 1.f, 1.f};
    int bx[3] = {0, 0, 0};
    for (int kk = 0; kk < K; kk++) {
        float g1 = sgx1[kk], g2 = sgy1[kk], g3 = sgx2[kk], g4 = sgy2[kk];
        float ga = sgar[kk];
        #pragma unroll
        for (int a = 0; a < 3; a++) {
            float lx = fmaxf(ax1[a], g1);
            float ly = fmaxf(ay1[a], g2);
            float rx = fminf(ax2[a], g3);
            float ry = fminf(ay2[a], g4);
            float w = fmaxf(rx - lx, 0.f);
            float h = fmaxf(ry - ly, 0.f);
            float in = w * h;
            float d = areaA[a] + ga - in + 1e-9f;
            if (in * bd[a] > bi[a] * d) { bi[a] = in; bd[a] = d; bx[a] = kk; }
        }
    }

    float acc = 0.f;
    int posc = 0;
    int hw = i * W + j;
    const float* pbb = pred + (size_t)b * 24 * HW + hw;

    #pragma unroll
    for (int a = 0; a < 3; a++) {
        float best = bi[a] / bd[a];   // one exact IEEE division per anchor
        bool pos = best >= 0.5f;
        bool neg = best < 0.4f;
        const float* pb = pbb + (size_t)(a * 8) * HW;
        float p4 = pb[(size_t)4 * HW];
        float obj = fmaxf(p4, 0.f) - (pos ? p4 : 0.f) + log1pf(expf(-fabsf(p4)));

        if (pos) {
            posc++;
            float q0 = pb[0];
            float q1 = pb[(size_t)HW];
            float q2 = pb[(size_t)2 * HW];
            float q3 = pb[(size_t)3 * HW];
            float q5 = pb[(size_t)5 * HW];
            float q6 = pb[(size_t)6 * HW];
            float q7 = pb[(size_t)7 * HW];
            int m = bx[a];
            float m0 = sgx1[m], m1 = sgy1[m], m2 = sgx2[m], m3 = sgy2[m];
            float ax = (ax1[a] + ax2[a]) * 0.5f;
            float ay = (ay1[a] + ay2[a]) * 0.5f;
            float aw = fmaxf(ax2[a] - ax1[a], 1e-6f);
            float ah = fmaxf(ay2[a] - ay1[a], 1e-6f);
            float gx = (m0 + m2) * 0.5f;
            float gy = (m1 + m3) * 0.5f;
            float gw = fmaxf(m2 - m0, 1e-6f);
            float gh = fmaxf(m3 - m1, 1e-6f);
            float loc = sl1(q0 - (gx - ax) / aw) + sl1(q1 - (gy - ay) / ah)
                      + sl1(q2 - logf(gw / aw)) + sl1(q3 - logf(gh / ah));
            float mx = fmaxf(q5, fmaxf(q6, q7));
            float lse = mx + logf(expf(q5 - mx) + expf(q6 - mx) + expf(q7 - mx));
            int tgt = slab[m]; if (tgt < 0) tgt = 0;
            float pt = (tgt == 0) ? q5 : ((tgt == 1) ? q6 : q7);
            acc += loc + obj + (lse - pt);
        }

        unsigned key = neg ? (__float_as_uint(obj) | 0x80000000u) : 0u;
        g_negkey[segoff + (size_t)b * (3 * HW) + (size_t)a * HW + hw] = key;

        // fused radix pass 3: top-byte histogram (warp-aggregated)
        unsigned bkt = key >> 24;
        unsigned mm = __match_any_sync(0xffffffffu, bkt);
        if ((tid & 31) == __ffs(mm) - 1)
            atomicAdd(&hist[bkt], (unsigned)__popc(mm));
    }

    // Block reduce loss partial + positive count; then flush histogram.
    float v = acc; int pc = posc;
    #pragma unroll
    for (int o = 16; o; o >>= 1) {
        v  += __shfl_down_sync(0xffffffffu, v, o);
        pc += __shfl_down_sync(0xffffffffu, pc, o);
    }
    if ((tid & 31) == 0) { rs[tid >> 5] = v; rp[tid >> 5] = pc; }
    __syncthreads();

    unsigned c = hist[tid];
    if (c) atomicAdd(&g_hist[(sIdx * 64 + b) * 256 + tid], c);

    if (tid < 32) {
        v  = (tid < 8) ? rs[tid] : 0.f;
        pc = (tid < 8) ? rp[tid] : 0;
        #pragma unroll
        for (int o = 4; o; o >>= 1) {
            v  += __shfl_down_sync(0xffffffffu, v, o);
            pc += __shfl_down_sync(0xffffffffu, pc, o);
        }
        if (tid == 0) {
            if (v != 0.f) atomicAdd(&g_total, v);
            if (pc)       atomicAdd(&g_numpos[sIdx * 64 + b], pc);
        }
    }
}

// Parallel byte-select: largest v with suffix-count >= kr (serial-walk
// semantics preserved: falls through to v=0 when the count runs out).
__device__ __forceinline__ void select256(const unsigned* cnt, int kr,
                                          int* s_v, int* s_kr, int tid)
{
    if (tid < 32) {
        int base = tid * 8;
        int seg = 0;
        #pragma unroll
        for (int t = 0; t < 8; t++) seg += (int)cnt[base + t];
        int incl = seg;
        #pragma unroll
        for (int off = 1; off < 32; off <<= 1) {
            int u = __shfl_down_sync(0xffffffffu, incl, off);
            if (tid + off < 32) incl += u;
        }
        int sufExcl = incl - seg;
        int total = __shfl_sync(0xffffffffu, incl, 0);
        if (sufExcl < kr && incl >= kr) {        // exactly one owner lane
            int cum = sufExcl;
            for (int t = 7; t >= 0; t--) {
                int cc = (int)cnt[base + t];
                if (cum + cc >= kr) { *s_v = base + t; *s_kr = kr - cum; break; }
                cum += cc;
            }
        }
        if (tid == 0 && total < kr) {            // k exceeds total keys
            *s_v = 0; *s_kr = kr - (total - (int)cnt[0]);
        }
    }
}

// One block per (b,scale): radix-select the k-th largest key (pass 3 fused
// into k_all; passes 2/1/0 scan once each while accumulating the sum of keys
// provably > T). Zeroes its g_hist slice for the next call. The last block
// out finalizes: writes the mean to out and resets g_total/g_numpos/g_done.
__global__ __launch_bounds__(1024) void k_select(float* __restrict__ out)
{
    int b = blockIdx.x, s = blockIdx.y;
    int N = (s == 0) ? 49152 : ((s == 1) ? 12288 : 3072);
    size_t off = (s == 0) ? 0
               : (s == 1) ? (size_t)64 * 49152
                          : (size_t)64 * (49152 + 12288);
    const unsigned* __restrict__ keys = g_negkey + off + (size_t)b * N;

    int np = g_numpos[s * 64 + b];
    int k = 3 * (np > 1 ? np : 1);

    __shared__ unsigned cnt[256];
    __shared__ float fsb[256];
    __shared__ int s_v, s_kr;
    __shared__ float red[32];

    int tid = threadIdx.x;
    int lane = tid & 31;
    int n4 = N >> 2;
    const uint4* k4 = (const uint4*)keys;

    // pass 3 from fused histogram (read, then zero for the next call)
    if (tid < 256) {
        int hidx = (s * 64 + b) * 256 + tid;
        cnt[tid] = g_hist[hidx];
        g_hist[hidx] = 0;
    }
    __syncthreads();
    select256(cnt, k, &s_v, &s_kr, tid);
    __syncthreads();
    unsigned v3 = (unsigned)s_v;
    int kr = s_kr;
    if (tid < 256) cnt[tid] = 0;
    __syncthreads();

    float lsum = 0.f;

    // pass 2
    for (int idx = tid; idx < n4; idx += 1024) {
        uint4 q = __ldg(k4 + idx);
        unsigned kk[4] = {q.x, q.y, q.z, q.w};
        #pragma unroll
        for (int e = 0; e < 4; e++) {
            unsigned key = kk[e];
            unsigned t = key >> 24;
            if (t > v3) lsum += __uint_as_float(key & 0x7fffffffu);
            else if (t == v3) {
                unsigned bkt = (key >> 16) & 255u;
                unsigned mm = __match_any_sync(__activemask(), bkt);
                if (lane == __ffs(mm) - 1)
                    atomicAdd(&cnt[bkt], (unsigned)__popc(mm));
            }
        }
    }
    __syncthreads();
    select256(cnt, kr, &s_v, &s_kr, tid);
    __syncthreads();
    unsigned p2 = (v3 << 8) | (unsigned)s_v;
    kr = s_kr;
    if (tid < 256) cnt[tid] = 0;
    __syncthreads();

    // pass 1
    for (int idx = tid; idx < n4; idx += 1024) {
        uint4 q = __ldg(k4 + idx);
        unsigned kk[4] = {q.x, q.y, q.z, q.w};
        #pragma unroll
        for (int e = 0; e < 4; e++) {
            unsigned key = kk[e];
            unsigned h = key >> 16;
            if (h == p2) {
                unsigned bkt = (key >> 8) & 255u;
                unsigned mm = __match_any_sync(__activemask(), bkt);
                if (lane == __ffs(mm) - 1)
                    atomicAdd(&cnt[bkt], (unsigned)__popc(mm));
            } else if ((key >> 24) == v3 && h > p2) {
                lsum += __uint_as_float(key & 0x7fffffffu);
            }
        }
    }
    __syncthreads();
    select256(cnt, kr, &s_v, &s_kr, tid);
    __syncthreads();
    unsigned p1 = (p2 << 8) | (unsigned)s_v;
    kr = s_kr;
    if (tid < 256) { cnt[tid] = 0; fsb[tid] = 0.f; }
    __syncthreads();

    // pass 0 (matching keys are few: plain atomics + per-bucket value sums)
    for (int idx = tid; idx < n4; idx += 1024) {
        uint4 q = __ldg(k4 + idx);
        unsigned kk[4] = {q.x, q.y, q.z, q.w};
        #pragma unroll
        for (int e = 0; e < 4; e++) {
            unsigned key = kk[e];
            unsigned q24 = key >> 8;
            if (q24 == p1) {
                unsigned bkt = key & 255u;
                atomicAdd(&cnt[bkt], 1u);
                atomicAdd(&fsb[bkt], __uint_as_float(key & 0x7fffffffu));
            } else if ((key >> 16) == p2 && q24 > p1) {
                lsum += __uint_as_float(key & 0x7fffffffu);
            }
        }
    }
    __syncthreads();
    select256(cnt, kr, &s_v, &s_kr, tid);
    __syncthreads();
    int v0 = s_v;
    int krF = s_kr;
    unsigned T = (p1 << 8) | (unsigned)v0;

    if (tid < 256 && tid > v0) lsum += fsb[tid];

    #pragma unroll
    for (int o = 16; o; o >>= 1) lsum += __shfl_down_sync(0xffffffffu, lsum, o);
    if (lane == 0) red[tid >> 5] = lsum;
    __syncthreads();
    if (tid < 32) {
        float v = red[tid];
        #pragma unroll
        for (int o = 16; o; o >>= 1) v += __shfl_down_sync(0xffffffffu, v, o);
        if (tid == 0) {
            if (T & 0x80000000u)   // real threshold -> ties contribute
                v += (float)krF * __uint_as_float(T & 0x7fffffffu);
            if (v != 0.f) atomicAdd(&g_total, v);

            // last-block-out finalizer (replaces k_final)
            __threadfence();
            unsigned done = atomicAdd(&g_done, 1u);
            if (done == 191u) {
                float tot = atomicAdd(&g_total, 0.0f);  // ordered read
                out[0] = tot * (1.0f / 64.0f);
                g_total = 0.0f;
                for (int z = 0; z < 192; z++) g_numpos[z] = 0;
                g_done = 0u;
            }
        }
    }
}

extern "C" void kernel_launch(void* const* d_in, const int* in_sizes, int n_in,
                              void* d_out, int out_size)
{
    const float *pred0 = 0, *pred1 = 0, *pred2 = 0, *gtb = 0;
    const int *gtl = 0;
    for (int i = 0; i < n_in; ++i) {
        switch (in_sizes[i]) {
            case 25165824: pred0 = (const float*)d_in[i]; break; // 64*24*128*128
            case 6291456:  pred1 = (const float*)d_in[i]; break; // 64*24*64*64
            case 1572864:  pred2 = (const float*)d_in[i]; break; // 64*24*32*32
            case 8192:     gtb   = (const float*)d_in[i]; break; // 64*32*4
            case 2048:     gtl   = (const int*)d_in[i];   break; // 64*32
        }
    }

    k_all<<<dim3(84, 64), 256>>>(pred0, pred1, pred2, gtb, gtl);
    k_select<<<dim3(64, 3), 1024>>>((float*)d_out);
}

// round 14
// speedup vs baseline: 2.6278x; 1.0395x over previous
#include <cuda_runtime.h>
#include <math.h>

#define NGT 32
#define NKEY (49152 + 12288 + 3072)

// Static scratch (no cudaMalloc anywhere). Zero-initialized at load;
// every kernel restores its state to zero each call (graph-replay safe).
__device__ unsigned g_negkey[64 * NKEY];
__device__ unsigned g_cand[64 * NKEY];      // pass-3 bucket candidates
__device__ unsigned g_hist[3 * 64 * 256];   // fused top-byte histogram
__device__ int      g_numpos[3 * 64];
__device__ float    g_total;
__device__ unsigned g_done;

__device__ __forceinline__ float sl1(float x) {
    float ax = fabsf(x);
    return ax < 1.0f ? 0.5f * x * x : ax - 0.5f;
}

// Fused matcher: ALL scales in one launch. blockIdx.x in [0,84):
//   [0,64)  scale 0: W=128, stride 8,  tiles 4x16
//   [64,80) scale 1: W=64,  stride 16, tiles 2x8
//   [80,84) scale 2: W=32,  stride 32, tiles 1x4
// Block = 32x8 grid positions of one image; thread = 1 position x 3 sizes.
__global__ __launch_bounds__(256) void k_all(
    const float* __restrict__ p0, const float* __restrict__ p1,
    const float* __restrict__ p2, const float* __restrict__ gtb,
    const int* __restrict__ gtl)
{
    __shared__ float sgx1[NGT], sgy1[NGT], sgx2[NGT], sgy2[NGT], sgar[NGT];
    __shared__ int slab[NGT];
    __shared__ int sK;
    __shared__ unsigned hist[256];
    __shared__ float rs[8];
    __shared__ int rp[8];

    int bs = blockIdx.x;
    int b = blockIdx.y;
    const float* pred;
    int W, tilesX, sIdx, tile;
    float stride;
    size_t segoff;
    if (bs < 64)      { pred = p0; W = 128; tilesX = 4; stride = 8.f;  sIdx = 0; segoff = 0;                            tile = bs; }
    else if (bs < 80) { pred = p1; W = 64;  tilesX = 2; stride = 16.f; sIdx = 1; segoff = (size_t)64 * 49152;           tile = bs - 64; }
    else              { pred = p2; W = 32;  tilesX = 1; stride = 32.f; sIdx = 2; segoff = (size_t)64 * (49152 + 12288); tile = bs - 80; }

    int ti = tile / tilesX;
    int tj = tile - ti * tilesX;
    int tid = threadIdx.x;
    int tx = tid & 31, ty = tid >> 5;
    int j = tj * 32 + tx;
    int i = ti * 8 + ty;
    int HW = W * W;

    hist[tid] = 0;

    // GT candidate compaction (warp 0). Tile bbox covers the largest anchor
    // half-extent (2.5*stride). Strict inequality: touching => IoU 0.
    if (tid < 32) {
        float xlo = (tj * 32 + 0.5f) * stride - 2.5f * stride;
        float xhi = (tj * 32 + 31.5f) * stride + 2.5f * stride;
        float ylo = (ti * 8 + 0.5f) * stride - 2.5f * stride;
        float yhi = (ti * 8 + 7.5f) * stride + 2.5f * stride;
        const float* g = gtb + ((size_t)b * NGT + tid) * 4;
        float gx1 = g[0], gy1 = g[1], gx2 = g[2], gy2 = g[3];
        bool ov = (gx1 < xhi) && (gx2 > xlo) && (gy1 < yhi) && (gy2 > ylo);
        unsigned m = __ballot_sync(0xffffffffu, ov);
        if (ov) {
            int p = __popc(m & ((1u << tid) - 1u));
            sgx1[p] = gx1; sgy1[p] = gy1; sgx2[p] = gx2; sgy2[p] = gy2;
            sgar[p] = (gx2 - gx1) * (gy2 - gy1);
            slab[p] = gtl[b * NGT + tid];
        }
        if (tid == 0) sK = __popc(m);
    }
    __syncthreads();
    int K = sK;

    float cpx = (j + 0.5f) * stride;
    float cpy = (i + 0.5f) * stride;
    float halfv[3] = {1.5f * stride, 2.0f * stride, 2.5f * stride};
    float ax1[3], ay1[3], ax2[3], ay2[3], areaA[3];
    #pragma unroll
    for (int a = 0; a < 3; a++) {
        ax1[a] = cpx - halfv[a]; ax2[a] = cpx + halfv[a];
        ay1[a] = cpy - halfv[a]; ay2[a] = cpy + halfv[a];
        float s2 = 2.0f * halfv[a];
        areaA[a] = s2 * s2;
    }

    // Division-free argmax; init (0, 1, idx 0) preserves argmax-first
    // semantics when all IoUs are 0.
    float bi[3] = {0.f, 0.f, 0.f}, bd[3] = {1.f, 1.f, 1.f};
    int bx[3] = {0, 0, 0};
    for (int kk = 0; kk < K; kk++) {
        float g1 = sgx1[kk], g2 = sgy1[kk], g3 = sgx2[kk], g4 = sgy2[kk];
        float ga = sgar[kk];
        #pragma unroll
        for (int a = 0; a < 3; a++) {
            float lx = fmaxf(ax1[a], g1);
            float ly = fmaxf(ay1[a], g2);
            float rx = fminf(ax2[a], g3);
            float ry = fminf(ay2[a], g4);
            float w = fmaxf(rx - lx, 0.f);
            float h = fmaxf(ry - ly, 0.f);
            float in = w * h;
            float d = areaA[a] + ga - in + 1e-9f;
            if (in * bd[a] > bi[a] * d) { bi[a] = in; bd[a] = d; bx[a] = kk; }
        }
    }

    float acc = 0.f;
    int posc = 0;
    int hw = i * W + j;
    const float* pbb = pred + (size_t)b * 24 * HW + hw;

    #pragma unroll
    for (int a = 0; a < 3; a++) {
        float best = bi[a] / bd[a];   // one exact IEEE division per anchor
        bool pos = best >= 0.5f;
        bool neg = best < 0.4f;
        const float* pb = pbb + (size_t)(a * 8) * HW;
        float p4 = pb[(size_t)4 * HW];
        // softplus via fast intrinsics: |err| ~1e-7 abs, far under tolerance
        float obj = fmaxf(p4, 0.f) - (pos ? p4 : 0.f)
                  + __logf(1.0f + __expf(-fabsf(p4)));

        if (pos) {
            posc++;
            float q0 = pb[0];
            float q1 = pb[(size_t)HW];
            float q2 = pb[(size_t)2 * HW];
            float q3 = pb[(size_t)3 * HW];
            float q5 = pb[(size_t)5 * HW];
            float q6 = pb[(size_t)6 * HW];
            float q7 = pb[(size_t)7 * HW];
            int m = bx[a];
            float m0 = sgx1[m], m1 = sgy1[m], m2 = sgx2[m], m3 = sgy2[m];
            float ax = (ax1[a] + ax2[a]) * 0.5f;
            float ay = (ay1[a] + ay2[a]) * 0.5f;
            float aw = fmaxf(ax2[a] - ax1[a], 1e-6f);
            float ah = fmaxf(ay2[a] - ay1[a], 1e-6f);
            float gx = (m0 + m2) * 0.5f;
            float gy = (m1 + m3) * 0.5f;
            float gw = fmaxf(m2 - m0, 1e-6f);
            float gh = fmaxf(m3 - m1, 1e-6f);
            float loc = sl1(q0 - (gx - ax) / aw) + sl1(q1 - (gy - ay) / ah)
                      + sl1(q2 - __logf(gw / aw)) + sl1(q3 - __logf(gh / ah));
            float mx = fmaxf(q5, fmaxf(q6, q7));
            float lse = mx + __logf(__expf(q5 - mx) + __expf(q6 - mx) + __expf(q7 - mx));
            int tgt = slab[m]; if (tgt < 0) tgt = 0;
            float pt = (tgt == 0) ? q5 : ((tgt == 1) ? q6 : q7);
            acc += loc + obj + (lse - pt);
        }

        unsigned key = neg ? (__float_as_uint(obj) | 0x80000000u) : 0u;
        g_negkey[segoff + (size_t)b * (3 * HW) + (size_t)a * HW + hw] = key;

        // fused radix pass 3: top-byte histogram (warp-aggregated)
        unsigned bkt = key >> 24;
        unsigned mm = __match_any_sync(0xffffffffu, bkt);
        if ((tid & 31) == __ffs(mm) - 1)
            atomicAdd(&hist[bkt], (unsigned)__popc(mm));
    }

    // Block reduce loss partial + positive count; then flush histogram.
    float v = acc; int pc = posc;
    #pragma unroll
    for (int o = 16; o; o >>= 1) {
        v  += __shfl_down_sync(0xffffffffu, v, o);
        pc += __shfl_down_sync(0xffffffffu, pc, o);
    }
    if ((tid & 31) == 0) { rs[tid >> 5] = v; rp[tid >> 5] = pc; }
    __syncthreads();

    unsigned c = hist[tid];
    if (c) atomicAdd(&g_hist[(sIdx * 64 + b) * 256 + tid], c);

    if (tid < 32) {
        v  = (tid < 8) ? rs[tid] : 0.f;
        pc = (tid < 8) ? rp[tid] : 0;
        #pragma unroll
        for (int o = 4; o; o >>= 1) {
            v  += __shfl_down_sync(0xffffffffu, v, o);
            pc += __shfl_down_sync(0xffffffffu, pc, o);
        }
        if (tid == 0) {
            if (v != 0.f) atomicAdd(&g_total, v);
            if (pc)       atomicAdd(&g_numpos[sIdx * 64 + b], pc);
        }
    }
}

// Parallel byte-select: largest v with suffix-count >= kr (serial-walk
// semantics preserved: falls through to v=0 when the count runs out).
__device__ __forceinline__ void select256(const unsigned* cnt, int kr,
                                          int* s_v, int* s_kr, int tid)
{
    if (tid < 32) {
        int base = tid * 8;
        int seg = 0;
        #pragma unroll
        for (int t = 0; t < 8; t++) seg += (int)cnt[base + t];
        int incl = seg;
        #pragma unroll
        for (int off = 1; off < 32; off <<= 1) {
            int u = __shfl_down_sync(0xffffffffu, incl, off);
            if (tid + off < 32) incl += u;
        }
        int sufExcl = incl - seg;
        int total = __shfl_sync(0xffffffffu, incl, 0);
        if (sufExcl < kr && incl >= kr) {        // exactly one owner lane
            int cum = sufExcl;
            for (int t = 7; t >= 0; t--) {
                int cc = (int)cnt[base + t];
                if (cum + cc >= kr) { *s_v = base + t; *s_kr = kr - cum; break; }
                cum += cc;
            }
        }
        if (tid == 0 && total < kr) {            // k exceeds total keys
            *s_v = 0; *s_kr = kr - (total - (int)cnt[0]);
        }
    }
}

// One block per (b,scale): radix-select the k-th largest key. Pass 3 is fused
// into k_all. Pass 2 makes the ONLY full key scan: it sums keys above the
// pass-3 bucket, histograms byte2 within it, and COMPACTS the bucket's keys
// (typically ~1-3K of N) into g_cand. Passes 1/0 then scan only candidates.
// Last block out finalizes: writes the mean and resets the accumulators.
__global__ __launch_bounds__(1024) void k_select(float* __restrict__ out)
{
    int b = blockIdx.x, s = blockIdx.y;
    int N = (s == 0) ? 49152 : ((s == 1) ? 12288 : 3072);
    size_t off = (s == 0) ? 0
               : (s == 1) ? (size_t)64 * 49152
                          : (size_t)64 * (49152 + 12288);
    const unsigned* __restrict__ keys = g_negkey + off + (size_t)b * N;
    unsigned* __restrict__ cand = g_cand + off + (size_t)b * N;

    int np = g_numpos[s * 64 + b];
    int k = 3 * (np > 1 ? np : 1);

    __shared__ unsigned cnt[256];
    __shared__ float fsb[256];
    __shared__ int s_v, s_kr, snc;
    __shared__ float red[32];

    int tid = threadIdx.x;
    int lane = tid & 31;
    int n4 = N >> 2;
    const uint4* k4 = (const uint4*)keys;

    // pass 3 from fused histogram (read, then zero for the next call)
    if (tid < 256) {
        int hidx = (s * 64 + b) * 256 + tid;
        cnt[tid] = g_hist[hidx];
        g_hist[hidx] = 0;
    }
    if (tid == 0) snc = 0;
    __syncthreads();
    select256(cnt, k, &s_v, &s_kr, tid);
    __syncthreads();
    unsigned v3 = (unsigned)s_v;
    int kr = s_kr;
    if (tid < 256) cnt[tid] = 0;
    __syncthreads();

    float lsum = 0.f;

    // pass 2: the only full scan. sum(top > v3) + hist(byte2 | top==v3)
    // + compact candidates (warp-aggregated shared-counter append).
    for (int idx = tid; idx < n4; idx += 1024) {
        uint4 q = __ldg(k4 + idx);
        unsigned kk[4] = {q.x, q.y, q.z, q.w};
        #pragma unroll
        for (int e = 0; e < 4; e++) {
            unsigned key = kk[e];
            unsigned t = key >> 24;
            if (t > v3) lsum += __uint_as_float(key & 0x7fffffffu);
            else if (t == v3) {
                unsigned am = __activemask();
                unsigned bkt = (key >> 16) & 255u;
                unsigned mm = __match_any_sync(am, bkt);
                if (lane == __ffs(mm) - 1)
                    atomicAdd(&cnt[bkt], (unsigned)__popc(mm));
                // compaction append
                int leader = __ffs(am) - 1;
                int base;
                if (lane == leader) base = atomicAdd(&snc, __popc(am));
                base = __shfl_sync(am, base, leader);
                base += __popc(am & ((1u << lane) - 1u));
                cand[base] = key;
            }
        }
    }
    __syncthreads();
    select256(cnt, kr, &s_v, &s_kr, tid);
    __syncthreads();
    unsigned v2 = (unsigned)s_v;
    kr = s_kr;
    int nc = snc;
    if (tid < 256) cnt[tid] = 0;
    __syncthreads();

    // pass 1: candidates only (all have top byte == v3)
    for (int i = tid; i < nc; i += 1024) {
        unsigned key = cand[i];
        unsigned b2 = (key >> 16) & 255u;
        if (b2 == v2) {
            unsigned am = __activemask();
            unsigned bkt = (key >> 8) & 255u;
            unsigned mm = __match_any_sync(am, bkt);
            if (lane == __ffs(mm) - 1)
                atomicAdd(&cnt[bkt], (unsigned)__popc(mm));
        } else if (b2 > v2) {
            lsum += __uint_as_float(key & 0x7fffffffu);
        }
    }
    __syncthreads();
    select256(cnt, kr, &s_v, &s_kr, tid);
    __syncthreads();
    unsigned v1 = (unsigned)s_v;
    kr = s_kr;
    if (tid < 256) { cnt[tid] = 0; fsb[tid] = 0.f; }
    __syncthreads();

    // pass 0: candidates only (few matches: plain atomics + value sums)
    for (int i = tid; i < nc; i += 1024) {
        unsigned key = cand[i];
        unsigned b2 = (key >> 16) & 255u;
        if (b2 == v2) {
            unsigned b1 = (key >> 8) & 255u;
            if (b1 == v1) {
                unsigned bkt = key & 255u;
                atomicAdd(&cnt[bkt], 1u);
                atomicAdd(&fsb[bkt], __uint_as_float(key & 0x7fffffffu));
            } else if (b1 > v1) {
                lsum += __uint_as_float(key & 0x7fffffffu);
            }
        }
    }
    __syncthreads();
    select256(cnt, kr, &s_v, &s_kr, tid);
    __syncthreads();
    int v0 = s_v;
    int krF = s_kr;
    unsigned T = (((v3 << 8) | v2) << 16) | (v1 << 8) | (unsigned)v0;

    if (tid < 256 && tid > v0) lsum += fsb[tid];

    #pragma unroll
    for (int o = 16; o; o >>= 1) lsum += __shfl_down_sync(0xffffffffu, lsum, o);
    if (lane == 0) red[tid >> 5] = lsum;
    __syncthreads();
    if (tid < 32) {
        float v = red[tid];
        #pragma unroll
        for (int o = 16; o; o >>= 1) v += __shfl_down_sync(0xffffffffu, v, o);
        if (tid == 0) {
            if (T & 0x80000000u)   // real threshold -> ties contribute
                v += (float)krF * __uint_as_float(T & 0x7fffffffu);
            if (v != 0.f) atomicAdd(&g_total, v);

            // last-block-out finalizer
            __threadfence();
            unsigned done = atomicAdd(&g_done, 1u);
            if (done == 191u) {
                float tot = atomicAdd(&g_total, 0.0f);  // ordered read
                out[0] = tot * (1.0f / 64.0f);
                g_total = 0.0f;
                for (int z = 0; z < 192; z++) g_numpos[z] = 0;
                g_done = 0u;
            }
        }
    }
}

extern "C" void kernel_launch(void* const* d_in, const int* in_sizes, int n_in,
                              void* d_out, int out_size)
{
    const float *pred0 = 0, *pred1 = 0, *pred2 = 0, *gtb = 0;
    const int *gtl = 0;
    for (int i = 0; i < n_in; ++i) {
        switch (in_sizes[i]) {
            case 25165824: pred0 = (const float*)d_in[i]; break; // 64*24*128*128
            case 6291456:  pred1 = (const float*)d_in[i]; break; // 64*24*64*64
            case 1572864:  pred2 = (const float*)d_in[i]; break; // 64*24*32*32
            case 8192:     gtb   = (const float*)d_in[i]; break; // 64*32*4
            case 2048:     gtl   = (const int*)d_in[i];   break; // 64*32
        }
    }

    k_all<<<dim3(84, 64), 256>>>(pred0, pred1, pred2, gtb, gtl);
    k_select<<<dim3(64, 3), 1024>>>((float*)d_out);
}